// round 1
// baseline (speedup 1.0000x reference)
#include <cuda_runtime.h>
#include <math.h>

// Problem constants (fixed by the reference)
#define T_TOK 8192          // B*S = 4*2048 tokens
#define HDIM  1024
#define NEXP  8
#define CAP   4096          // per-expert token capacity (expected ~2048)

// GEMM tiling
#define TM 128
#define TN 128
#define TK 16
#define SPAD 4

// ---------------- scratch (device globals; no runtime allocation) ----------
__device__ int   g_cnt[NEXP];
__device__ int   g_tok[NEXP * CAP];
__device__ float g_wgt[NEXP * CAP];
__device__ float g_h1[(size_t)NEXP * CAP * HDIM];   // 128 MiB

// ---------------- router: logits -> softmax -> top2 -> expert lists --------
__global__ __launch_bounds__(256) void router_kernel(
    const float* __restrict__ x, const float* __restrict__ rw,
    float* __restrict__ out, int write_probs)
{
    int warp_in_blk = threadIdx.x >> 5;
    int t = blockIdx.x * 8 + warp_in_blk;
    if (t >= T_TOK) return;
    int lane = threadIdx.x & 31;

    float acc[NEXP];
#pragma unroll
    for (int e = 0; e < NEXP; e++) acc[e] = 0.f;

    const float* xp = x + (size_t)t * HDIM;
    for (int i = lane; i < HDIM; i += 32) {
        float xv = xp[i];
#pragma unroll
        for (int e = 0; e < NEXP; e++)
            acc[e] = fmaf(xv, rw[e * HDIM + i], acc[e]);
    }
#pragma unroll
    for (int e = 0; e < NEXP; e++) {
#pragma unroll
        for (int off = 16; off; off >>= 1)
            acc[e] += __shfl_xor_sync(0xffffffffu, acc[e], off);
    }

    if (lane == 0) {
        float m = acc[0];
#pragma unroll
        for (int e = 1; e < NEXP; e++) m = fmaxf(m, acc[e]);
        float p[NEXP]; float s = 0.f;
#pragma unroll
        for (int e = 0; e < NEXP; e++) { p[e] = expf(acc[e] - m); s += p[e]; }
        float inv_s = 1.f / s;
#pragma unroll
        for (int e = 0; e < NEXP; e++) p[e] *= inv_s;

        if (write_probs) {
            float* pr = out + (size_t)T_TOK * HDIM + (size_t)t * NEXP;
#pragma unroll
            for (int e = 0; e < NEXP; e++) pr[e] = p[e];
        }

        // top-2 (first-index tie-break, like jax top_k)
        int i0 = 0;
#pragma unroll
        for (int e = 1; e < NEXP; e++) if (p[e] > p[i0]) i0 = e;
        int i1 = (i0 == 0) ? 1 : 0;
#pragma unroll
        for (int e = 0; e < NEXP; e++) if (e != i0 && p[e] > p[i1]) i1 = e;

        float v0 = p[i0], v1 = p[i1];
        float invw = 1.f / (v0 + v1);
        float w0 = v0 * invw, w1 = v1 * invw;

        int pos0 = atomicAdd(&g_cnt[i0], 1);
        if (pos0 < CAP) { g_tok[i0 * CAP + pos0] = t; g_wgt[i0 * CAP + pos0] = w0; }
        int pos1 = atomicAdd(&g_cnt[i1], 1);
        if (pos1 < CAP) { g_tok[i1 * CAP + pos1] = t; g_wgt[i1 * CAP + pos1] = w1; }
    }
}

// ---------------- GEMM1: h1 = relu(x_gathered @ W1^T + b1) -----------------
__global__ __launch_bounds__(256) void gemm1_kernel(
    const float* __restrict__ x, const float* __restrict__ W1,
    const float* __restrict__ b1)
{
    int e = blockIdx.z;
    int count = min(g_cnt[e], CAP);
    int m0 = blockIdx.y * TM;
    if (m0 >= count) return;
    int n0 = blockIdx.x * TN;

    __shared__ float As[TK][TM + SPAD];
    __shared__ float Bs[TK][TN + SPAD];

    int tid = threadIdx.x;
    int warp = tid >> 5, lane = tid & 31;
    int wy = warp & 3, wx = warp >> 2;
    int ly = lane >> 3, lx = lane & 7;
    int row0 = wy * 32 + ly * 8;
    int col0 = wx * 64 + lx * 8;

    int arow0 = tid >> 2,          akq0 = tid & 3;
    int arow1 = (tid + 256) >> 2,  akq1 = (tid + 256) & 3;

    int tokA0 = (m0 + arow0 < count) ? g_tok[e * CAP + m0 + arow0] : -1;
    int tokA1 = (m0 + arow1 < count) ? g_tok[e * CAP + m0 + arow1] : -1;

    const float* Wb = W1 + ((size_t)e * HDIM + n0) * HDIM;

    float acc[8][8];
#pragma unroll
    for (int i = 0; i < 8; i++)
#pragma unroll
        for (int j = 0; j < 8; j++) acc[i][j] = 0.f;

    for (int k0 = 0; k0 < HDIM; k0 += TK) {
        float4 a0 = make_float4(0.f, 0.f, 0.f, 0.f), a1 = a0;
        if (tokA0 >= 0) a0 = *(const float4*)(x + (size_t)tokA0 * HDIM + k0 + akq0 * 4);
        if (tokA1 >= 0) a1 = *(const float4*)(x + (size_t)tokA1 * HDIM + k0 + akq1 * 4);
        float4 w0 = *(const float4*)(Wb + (size_t)arow0 * HDIM + k0 + akq0 * 4);
        float4 w1 = *(const float4*)(Wb + (size_t)arow1 * HDIM + k0 + akq1 * 4);

        __syncthreads();
        As[akq0 * 4 + 0][arow0] = a0.x; As[akq0 * 4 + 1][arow0] = a0.y;
        As[akq0 * 4 + 2][arow0] = a0.z; As[akq0 * 4 + 3][arow0] = a0.w;
        As[akq1 * 4 + 0][arow1] = a1.x; As[akq1 * 4 + 1][arow1] = a1.y;
        As[akq1 * 4 + 2][arow1] = a1.z; As[akq1 * 4 + 3][arow1] = a1.w;
        Bs[akq0 * 4 + 0][arow0] = w0.x; Bs[akq0 * 4 + 1][arow0] = w0.y;
        Bs[akq0 * 4 + 2][arow0] = w0.z; Bs[akq0 * 4 + 3][arow0] = w0.w;
        Bs[akq1 * 4 + 0][arow1] = w1.x; Bs[akq1 * 4 + 1][arow1] = w1.y;
        Bs[akq1 * 4 + 2][arow1] = w1.z; Bs[akq1 * 4 + 3][arow1] = w1.w;
        __syncthreads();

#pragma unroll
        for (int kk = 0; kk < TK; kk++) {
            float4 av0 = *(const float4*)&As[kk][row0];
            float4 av1 = *(const float4*)&As[kk][row0 + 4];
            float4 bv0 = *(const float4*)&Bs[kk][col0];
            float4 bv1 = *(const float4*)&Bs[kk][col0 + 4];
            float a[8] = {av0.x, av0.y, av0.z, av0.w, av1.x, av1.y, av1.z, av1.w};
            float b[8] = {bv0.x, bv0.y, bv0.z, bv0.w, bv1.x, bv1.y, bv1.z, bv1.w};
#pragma unroll
            for (int i = 0; i < 8; i++)
#pragma unroll
                for (int j = 0; j < 8; j++)
                    acc[i][j] = fmaf(a[i], b[j], acc[i][j]);
        }
    }

#pragma unroll
    for (int i = 0; i < 8; i++) {
        int r = m0 + row0 + i;
        if (r < count) {
            float* dst = g_h1 + ((size_t)e * CAP + r) * HDIM + n0;
#pragma unroll
            for (int j = 0; j < 8; j++) {
                int c = col0 + j;
                float v = acc[i][j] + b1[e * HDIM + n0 + c];
                dst[c] = fmaxf(v, 0.f);
            }
        }
    }
}

// ---------------- GEMM2: out += w * (h1 @ W2^T + b2) -----------------------
__global__ __launch_bounds__(256) void gemm2_kernel(
    const float* __restrict__ W2, const float* __restrict__ b2,
    float* __restrict__ out)
{
    int e = blockIdx.z;
    int count = min(g_cnt[e], CAP);
    int m0 = blockIdx.y * TM;
    if (m0 >= count) return;
    int n0 = blockIdx.x * TN;

    __shared__ float As[TK][TM + SPAD];
    __shared__ float Bs[TK][TN + SPAD];

    int tid = threadIdx.x;
    int warp = tid >> 5, lane = tid & 31;
    int wy = warp & 3, wx = warp >> 2;
    int ly = lane >> 3, lx = lane & 7;
    int row0 = wy * 32 + ly * 8;
    int col0 = wx * 64 + lx * 8;

    int arow0 = tid >> 2,          akq0 = tid & 3;
    int arow1 = (tid + 256) >> 2,  akq1 = (tid + 256) & 3;

    bool va0 = (m0 + arow0 < count);
    bool va1 = (m0 + arow1 < count);
    const float* Ab = g_h1 + ((size_t)e * CAP + m0) * HDIM;
    const float* Wb = W2 + ((size_t)e * HDIM + n0) * HDIM;

    float acc[8][8];
#pragma unroll
    for (int i = 0; i < 8; i++)
#pragma unroll
        for (int j = 0; j < 8; j++) acc[i][j] = 0.f;

    for (int k0 = 0; k0 < HDIM; k0 += TK) {
        float4 a0 = make_float4(0.f, 0.f, 0.f, 0.f), a1 = a0;
        if (va0) a0 = *(const float4*)(Ab + (size_t)arow0 * HDIM + k0 + akq0 * 4);
        if (va1) a1 = *(const float4*)(Ab + (size_t)arow1 * HDIM + k0 + akq1 * 4);
        float4 w0 = *(const float4*)(Wb + (size_t)arow0 * HDIM + k0 + akq0 * 4);
        float4 w1 = *(const float4*)(Wb + (size_t)arow1 * HDIM + k0 + akq1 * 4);

        __syncthreads();
        As[akq0 * 4 + 0][arow0] = a0.x; As[akq0 * 4 + 1][arow0] = a0.y;
        As[akq0 * 4 + 2][arow0] = a0.z; As[akq0 * 4 + 3][arow0] = a0.w;
        As[akq1 * 4 + 0][arow1] = a1.x; As[akq1 * 4 + 1][arow1] = a1.y;
        As[akq1 * 4 + 2][arow1] = a1.z; As[akq1 * 4 + 3][arow1] = a1.w;
        Bs[akq0 * 4 + 0][arow0] = w0.x; Bs[akq0 * 4 + 1][arow0] = w0.y;
        Bs[akq0 * 4 + 2][arow0] = w0.z; Bs[akq0 * 4 + 3][arow0] = w0.w;
        Bs[akq1 * 4 + 0][arow1] = w1.x; Bs[akq1 * 4 + 1][arow1] = w1.y;
        Bs[akq1 * 4 + 2][arow1] = w1.z; Bs[akq1 * 4 + 3][arow1] = w1.w;
        __syncthreads();

#pragma unroll
        for (int kk = 0; kk < TK; kk++) {
            float4 av0 = *(const float4*)&As[kk][row0];
            float4 av1 = *(const float4*)&As[kk][row0 + 4];
            float4 bv0 = *(const float4*)&Bs[kk][col0];
            float4 bv1 = *(const float4*)&Bs[kk][col0 + 4];
            float a[8] = {av0.x, av0.y, av0.z, av0.w, av1.x, av1.y, av1.z, av1.w};
            float b[8] = {bv0.x, bv0.y, bv0.z, bv0.w, bv1.x, bv1.y, bv1.z, bv1.w};
#pragma unroll
            for (int i = 0; i < 8; i++)
#pragma unroll
                for (int j = 0; j < 8; j++)
                    acc[i][j] = fmaf(a[i], b[j], acc[i][j]);
        }
    }

#pragma unroll
    for (int i = 0; i < 8; i++) {
        int r = m0 + row0 + i;
        if (r < count) {
            int tok = g_tok[e * CAP + r];
            float w = g_wgt[e * CAP + r];
            float* dst = out + (size_t)tok * HDIM + n0;
#pragma unroll
            for (int j = 0; j < 8; j++) {
                int c = col0 + j;
                float v = (acc[i][j] + b2[e * HDIM + n0 + c]) * w;
                atomicAdd(dst + c, v);
            }
        }
    }
}

// ---------------- launch ---------------------------------------------------
extern "C" void kernel_launch(void* const* d_in, const int* in_sizes, int n_in,
                              void* d_out, int out_size)
{
    const float* x   = (const float*)d_in[0];
    const float* rw  = (const float*)d_in[1];
    const float* W1  = (const float*)d_in[2];
    const float* b1  = (const float*)d_in[3];
    const float* W2  = (const float*)d_in[4];
    const float* b2  = (const float*)d_in[5];
    float* out = (float*)d_out;

    void* cnt_addr = nullptr;
    cudaGetSymbolAddress(&cnt_addr, g_cnt);
    cudaMemsetAsync(cnt_addr, 0, NEXP * sizeof(int), 0);

    // out[0 : T*H] starts as hidden_states (residual); GEMM2 accumulates into it
    cudaMemcpyAsync(out, x, (size_t)T_TOK * HDIM * sizeof(float),
                    cudaMemcpyDeviceToDevice, 0);

    int write_probs = (out_size >= T_TOK * HDIM + T_TOK * NEXP) ? 1 : 0;
    router_kernel<<<T_TOK / 8, 256>>>(x, rw, out, write_probs);

    dim3 grid(HDIM / TN, CAP / TM, NEXP);
    gemm1_kernel<<<grid, 256>>>(x, W1, b1);
    gemm2_kernel<<<grid, 256>>>(W2, b2, out);
}

// round 3
// speedup vs baseline: 2.7060x; 2.7060x over previous
#include <cuda_runtime.h>
#include <cstdint>
#include <math.h>

// Problem constants
#define T_TOK 8192
#define HDIM  1024
#define NEXP  8
#define CAP   4096

// GEMM tiling: CTA 128x128, 4 warps of 64x64, K-chunk 32
#define TM 128
#define TN 128
#define KC 32
#define NCH (HDIM / KC)          // 32 chunks
#define ABLK 16384               // bytes per A (or B) chunk block: 2 subs x 8KB
#define BUFB 32768               // bytes per buffer (A block + B block)
#define SMEM_BYTES (2 * BUFB)    // 64 KB

// ---------------- scratch ----------------------------------------------------
__device__ int   g_cnt[NEXP];
__device__ int   g_tok[NEXP * CAP];
__device__ float g_wgt[NEXP * CAP];
__device__ float g_h1[(size_t)NEXP * CAP * HDIM];   // 128 MiB

// ---------------- helpers ----------------------------------------------------
__device__ __forceinline__ uint32_t smem_u32(const void* p) {
    uint32_t a;
    asm("{ .reg .u64 t; cvta.to.shared.u64 t, %1; cvt.u32.u64 %0, t; }" : "=r"(a) : "l"(p));
    return a;
}
__device__ __forceinline__ uint32_t f2tf32(float v) {
    uint32_t r;
    asm("cvt.rna.tf32.f32 %0, %1;" : "=r"(r) : "f"(v));
    return r;
}
__device__ __forceinline__ void sts32(uint32_t addr, uint32_t v) {
    asm volatile("st.shared.b32 [%0], %1;" :: "r"(addr), "r"(v));
}
__device__ __forceinline__ uint4 lds128(uint32_t addr) {
    uint4 v;
    asm volatile("ld.shared.v4.b32 {%0,%1,%2,%3}, [%4];"
                 : "=r"(v.x), "=r"(v.y), "=r"(v.z), "=r"(v.w) : "r"(addr));
    return v;
}
__device__ __forceinline__ void mma8(float* c,
    uint32_t a0, uint32_t a1, uint32_t a2, uint32_t a3, uint32_t b0, uint32_t b1)
{
    asm volatile(
        "mma.sync.aligned.m16n8k8.row.col.f32.tf32.tf32.f32 "
        "{%0,%1,%2,%3}, {%4,%5,%6,%7}, {%8,%9}, {%0,%1,%2,%3};"
        : "+f"(c[0]), "+f"(c[1]), "+f"(c[2]), "+f"(c[3])
        : "r"(a0), "r"(a1), "r"(a2), "r"(a3), "r"(b0), "r"(b1));
}

// ---------------- router ------------------------------------------------------
__global__ __launch_bounds__(256) void router_kernel(
    const float* __restrict__ x, const float* __restrict__ rw,
    float* __restrict__ out, int write_probs)
{
    int t = blockIdx.x * 8 + (threadIdx.x >> 5);
    if (t >= T_TOK) return;
    int lane = threadIdx.x & 31;

    float acc[NEXP];
#pragma unroll
    for (int e = 0; e < NEXP; e++) acc[e] = 0.f;
    const float* xp = x + (size_t)t * HDIM;
    for (int i = lane; i < HDIM; i += 32) {
        float xv = xp[i];
#pragma unroll
        for (int e = 0; e < NEXP; e++)
            acc[e] = fmaf(xv, rw[e * HDIM + i], acc[e]);
    }
#pragma unroll
    for (int e = 0; e < NEXP; e++)
#pragma unroll
        for (int off = 16; off; off >>= 1)
            acc[e] += __shfl_xor_sync(0xffffffffu, acc[e], off);

    if (lane == 0) {
        float m = acc[0];
#pragma unroll
        for (int e = 1; e < NEXP; e++) m = fmaxf(m, acc[e]);
        float p[NEXP]; float s = 0.f;
#pragma unroll
        for (int e = 0; e < NEXP; e++) { p[e] = expf(acc[e] - m); s += p[e]; }
        float inv_s = 1.f / s;
#pragma unroll
        for (int e = 0; e < NEXP; e++) p[e] *= inv_s;

        if (write_probs) {
            float* pr = out + (size_t)T_TOK * HDIM + (size_t)t * NEXP;
#pragma unroll
            for (int e = 0; e < NEXP; e++) pr[e] = p[e];
        }
        int i0 = 0;
#pragma unroll
        for (int e = 1; e < NEXP; e++) if (p[e] > p[i0]) i0 = e;
        int i1 = (i0 == 0) ? 1 : 0;
#pragma unroll
        for (int e = 0; e < NEXP; e++) if (e != i0 && p[e] > p[i1]) i1 = e;

        float v0 = p[i0], v1 = p[i1];
        float invw = 1.f / (v0 + v1);
        int pos0 = atomicAdd(&g_cnt[i0], 1);
        if (pos0 < CAP) { g_tok[i0 * CAP + pos0] = t; g_wgt[i0 * CAP + pos0] = v0 * invw; }
        int pos1 = atomicAdd(&g_cnt[i1], 1);
        if (pos1 < CAP) { g_tok[i1 * CAP + pos1] = t; g_wgt[i1 * CAP + pos1] = v1 * invw; }
    }
}

// ---------------- chunk loader: gmem -> permuted/swizzled smem ---------------
// Thread t handles rows {t>>3 + 16i, i=0..7}, 16B column kq = t&7 of the chunk.
// Smem layout per block: sub(0,1)*8192 + row*64 + csw*16 + (kq&3)*4,
//   csw = (j ^ (row&3) ^ sub) & 3   (j = element index in the float4)
__device__ __forceinline__ void load_chunk(
    uint32_t sbuf,                       // smem byte base of buffer (A block; B at +ABLK)
    const float* __restrict__ abase, const uint32_t aoff[8],
    const float* __restrict__ bbase, const uint32_t boff[8],
    int c, int tid)
{
    int rbase = tid >> 3, kq = tid & 7;
    int sub = kq >> 2, q3 = kq & 3, rm3 = rbase & 3;
    uint32_t base = sbuf + sub * 8192 + rbase * 64 + q3 * 4;
    uint32_t cs0 = ((0 ^ rm3 ^ sub) & 3) * 16;
    uint32_t cs1 = ((1 ^ rm3 ^ sub) & 3) * 16;
    uint32_t cs2 = ((2 ^ rm3 ^ sub) & 3) * 16;
    uint32_t cs3 = ((3 ^ rm3 ^ sub) & 3) * 16;

#pragma unroll
    for (int i = 0; i < 8; i++) {
        float4 v = __ldg((const float4*)(abase + aoff[i] + c * KC));
        uint32_t d = base + i * 1024;
        sts32(d + cs0, f2tf32(v.x)); sts32(d + cs1, f2tf32(v.y));
        sts32(d + cs2, f2tf32(v.z)); sts32(d + cs3, f2tf32(v.w));
    }
#pragma unroll
    for (int i = 0; i < 8; i++) {
        float4 v = __ldg((const float4*)(bbase + boff[i] + c * KC));
        uint32_t d = base + ABLK + i * 1024;
        sts32(d + cs0, f2tf32(v.x)); sts32(d + cs1, f2tf32(v.y));
        sts32(d + cs2, f2tf32(v.z)); sts32(d + cs3, f2tf32(v.w));
    }
}

// ---------------- compute one chunk (4 k-steps of 8) -------------------------
__device__ __forceinline__ void compute_chunk(
    uint32_t sbuf, float acc[4][8][4], int warp_m, int warp_n, int gid, int tig)
{
#pragma unroll
    for (int sub = 0; sub < 2; sub++) {
        uint32_t ct = ((tig ^ (gid & 3) ^ sub) & 3) * 16;
        uint32_t abase = sbuf + sub * 8192 + (warp_m * 64 + gid) * 64 + ct;
        uint32_t bbase = sbuf + ABLK + sub * 8192 + (warp_n * 64 + gid) * 64 + ct;

        uint4 fa_lo[4], fa_hi[4], fb[8];
#pragma unroll
        for (int mi = 0; mi < 4; mi++) {
            fa_lo[mi] = lds128(abase + mi * 1024);
            fa_hi[mi] = lds128(abase + mi * 1024 + 512);
        }
#pragma unroll
        for (int ni = 0; ni < 8; ni++)
            fb[ni] = lds128(bbase + ni * 512);

        // k-step 0 (elements .x/.y), k-step 1 (.z/.w)
#pragma unroll
        for (int mi = 0; mi < 4; mi++)
#pragma unroll
            for (int ni = 0; ni < 8; ni++)
                mma8(acc[mi][ni], fa_lo[mi].x, fa_hi[mi].x, fa_lo[mi].y, fa_hi[mi].y,
                     fb[ni].x, fb[ni].y);
#pragma unroll
        for (int mi = 0; mi < 4; mi++)
#pragma unroll
            for (int ni = 0; ni < 8; ni++)
                mma8(acc[mi][ni], fa_lo[mi].z, fa_hi[mi].z, fa_lo[mi].w, fa_hi[mi].w,
                     fb[ni].z, fb[ni].w);
    }
}

// ---------------- GEMM1: g_h1 = relu(x[gather] @ W1^T + b1) ------------------
__global__ __launch_bounds__(128) void gemm1_tc(
    const float* __restrict__ x, const float* __restrict__ W1,
    const float* __restrict__ b1)
{
    extern __shared__ char smem[];
    int e = blockIdx.z;
    int count = min(g_cnt[e], CAP);
    int m0 = blockIdx.y * TM;
    if (m0 >= count) return;
    int n0 = blockIdx.x * TN;

    uint32_t sb = smem_u32(smem);
    int tid = threadIdx.x, wid = tid >> 5, lane = tid & 31;
    int warp_m = wid >> 1, warp_n = wid & 1;
    int gid = lane >> 2, tig = lane & 3;

    // load offsets (element units)
    int rbase = tid >> 3, kq = tid & 7;
    uint32_t aoff[8], boff[8];
#pragma unroll
    for (int i = 0; i < 8; i++) {
        int row = rbase + 16 * i;
        int tok = g_tok[e * CAP + m0 + row];     // stale slots: finite garbage, masked later
        aoff[i] = (uint32_t)tok * HDIM + kq * 4;
        boff[i] = (uint32_t)((e * HDIM + n0 + row)) * HDIM + kq * 4;
    }

    float acc[4][8][4];
#pragma unroll
    for (int mi = 0; mi < 4; mi++)
#pragma unroll
        for (int ni = 0; ni < 8; ni++)
#pragma unroll
            for (int q = 0; q < 4; q++) acc[mi][ni][q] = 0.f;

    load_chunk(sb, x, aoff, W1, boff, 0, tid);
    __syncthreads();
    for (int c = 0; c < NCH; c++) {
        if (c + 1 < NCH)
            load_chunk(sb + ((c + 1) & 1) * BUFB, x, aoff, W1, boff, c + 1, tid);
        compute_chunk(sb + (c & 1) * BUFB, acc, warp_m, warp_n, gid, tig);
        __syncthreads();
    }

    // epilogue: relu(acc + b1) -> g_h1
    const float* bb = b1 + e * HDIM + n0 + warp_n * 64 + tig * 2;
#pragma unroll
    for (int mi = 0; mi < 4; mi++) {
        int r0 = m0 + warp_m * 64 + mi * 16 + gid;
        int r1 = r0 + 8;
        float* d0 = g_h1 + ((size_t)e * CAP + r0) * HDIM + n0 + warp_n * 64 + tig * 2;
        float* d1 = g_h1 + ((size_t)e * CAP + r1) * HDIM + n0 + warp_n * 64 + tig * 2;
#pragma unroll
        for (int ni = 0; ni < 8; ni++) {
            float2 bv = *(const float2*)(bb + ni * 8);
            if (r0 < count) {
                float2 o;
                o.x = fmaxf(acc[mi][ni][0] + bv.x, 0.f);
                o.y = fmaxf(acc[mi][ni][1] + bv.y, 0.f);
                *(float2*)(d0 + ni * 8) = o;
            }
            if (r1 < count) {
                float2 o;
                o.x = fmaxf(acc[mi][ni][2] + bv.x, 0.f);
                o.y = fmaxf(acc[mi][ni][3] + bv.y, 0.f);
                *(float2*)(d1 + ni * 8) = o;
            }
        }
    }
}

// ---------------- GEMM2: out[tok] += w * (g_h1 @ W2^T + b2) ------------------
__global__ __launch_bounds__(128) void gemm2_tc(
    const float* __restrict__ W2, const float* __restrict__ b2,
    float* __restrict__ out)
{
    extern __shared__ char smem[];
    int e = blockIdx.z;
    int count = min(g_cnt[e], CAP);
    int m0 = blockIdx.y * TM;
    if (m0 >= count) return;
    int n0 = blockIdx.x * TN;

    uint32_t sb = smem_u32(smem);
    int tid = threadIdx.x, wid = tid >> 5, lane = tid & 31;
    int warp_m = wid >> 1, warp_n = wid & 1;
    int gid = lane >> 2, tig = lane & 3;

    int rbase = tid >> 3, kq = tid & 7;
    uint32_t aoff[8], boff[8];
#pragma unroll
    for (int i = 0; i < 8; i++) {
        int row = rbase + 16 * i;
        aoff[i] = (uint32_t)((e * CAP + m0 + row)) * HDIM + kq * 4;
        boff[i] = (uint32_t)((e * HDIM + n0 + row)) * HDIM + kq * 4;
    }

    float acc[4][8][4];
#pragma unroll
    for (int mi = 0; mi < 4; mi++)
#pragma unroll
        for (int ni = 0; ni < 8; ni++)
#pragma unroll
            for (int q = 0; q < 4; q++) acc[mi][ni][q] = 0.f;

    load_chunk(sb, g_h1, aoff, W2, boff, 0, tid);
    __syncthreads();
    for (int c = 0; c < NCH; c++) {
        if (c + 1 < NCH)
            load_chunk(sb + ((c + 1) & 1) * BUFB, g_h1, aoff, W2, boff, c + 1, tid);
        compute_chunk(sb + (c & 1) * BUFB, acc, warp_m, warp_n, gid, tig);
        __syncthreads();
    }

    // epilogue: out[tok] += w * (acc + b2)
    const float* bb = b2 + e * HDIM + n0 + warp_n * 64 + tig * 2;
#pragma unroll
    for (int mi = 0; mi < 4; mi++) {
        int r0 = m0 + warp_m * 64 + mi * 16 + gid;
        int r1 = r0 + 8;
        int tok0 = g_tok[e * CAP + r0], tok1 = g_tok[e * CAP + r1];
        float w0 = g_wgt[e * CAP + r0], w1 = g_wgt[e * CAP + r1];
        float* d0 = out + (size_t)tok0 * HDIM + n0 + warp_n * 64 + tig * 2;
        float* d1 = out + (size_t)tok1 * HDIM + n0 + warp_n * 64 + tig * 2;
#pragma unroll
        for (int ni = 0; ni < 8; ni++) {
            float2 bv = *(const float2*)(bb + ni * 8);
            if (r0 < count) {
                atomicAdd(d0 + ni * 8 + 0, (acc[mi][ni][0] + bv.x) * w0);
                atomicAdd(d0 + ni * 8 + 1, (acc[mi][ni][1] + bv.y) * w0);
            }
            if (r1 < count) {
                atomicAdd(d1 + ni * 8 + 0, (acc[mi][ni][2] + bv.x) * w1);
                atomicAdd(d1 + ni * 8 + 1, (acc[mi][ni][3] + bv.y) * w1);
            }
        }
    }
}

// ---------------- launch ------------------------------------------------------
extern "C" void kernel_launch(void* const* d_in, const int* in_sizes, int n_in,
                              void* d_out, int out_size)
{
    const float* x  = (const float*)d_in[0];
    const float* rw = (const float*)d_in[1];
    const float* W1 = (const float*)d_in[2];
    const float* b1 = (const float*)d_in[3];
    const float* W2 = (const float*)d_in[4];
    const float* b2 = (const float*)d_in[5];
    float* out = (float*)d_out;

    void* cnt_addr = nullptr;
    cudaGetSymbolAddress(&cnt_addr, g_cnt);
    cudaMemsetAsync(cnt_addr, 0, NEXP * sizeof(int), 0);

    // residual: out starts as hidden_states; GEMM2 accumulates into it
    cudaMemcpyAsync(out, x, (size_t)T_TOK * HDIM * sizeof(float),
                    cudaMemcpyDeviceToDevice, 0);

    int write_probs = (out_size >= T_TOK * HDIM + T_TOK * NEXP) ? 1 : 0;
    router_kernel<<<T_TOK / 8, 256>>>(x, rw, out, write_probs);

    cudaFuncSetAttribute(gemm1_tc, cudaFuncAttributeMaxDynamicSharedMemorySize, SMEM_BYTES);
    cudaFuncSetAttribute(gemm2_tc, cudaFuncAttributeMaxDynamicSharedMemorySize, SMEM_BYTES);

    dim3 grid(HDIM / TN, CAP / TM, NEXP);
    gemm1_tc<<<grid, 128, SMEM_BYTES>>>(x, W1, b1);
    gemm2_tc<<<grid, 128, SMEM_BYTES>>>(W2, b2, out);
}

// round 4
// speedup vs baseline: 3.5359x; 1.3067x over previous
#include <cuda_runtime.h>
#include <cuda_bf16.h>
#include <cstdint>
#include <math.h>

// Problem constants
#define T_TOK 8192
#define HDIM  1024
#define NEXP  8
#define CAP   4096

// GEMM tiling: CTA 128x128, 8 warps of 32x64, K-chunk 32, 4-stage cp.async
#define TM 128
#define TN 128
#define KC 32
#define NCH 32
#define STAGE_BYTES 16384           // A 8KB + B 8KB (bf16, 64B per 32-k row)
#define SMEM_BYTES (4 * STAGE_BYTES)

// ---------------- scratch (device globals, zero-init at load) ---------------
__device__ int   g_cnt[NEXP];
__device__ int   g_tok[NEXP * CAP];
__device__ float g_wgt[NEXP * CAP];
__device__ uint4 g_xb [(size_t)T_TOK * 128];        // 16MB bf16 permuted x
__device__ uint4 g_w1b[(size_t)NEXP * HDIM * 128];  // 16MB
__device__ uint4 g_w2b[(size_t)NEXP * HDIM * 128];  // 16MB
__device__ uint4 g_h1b[(size_t)NEXP * CAP * 128];   // 64MB bf16 permuted h1

// ---------------- helpers ----------------------------------------------------
__device__ __forceinline__ uint32_t smem_u32(const void* p) {
    uint32_t a;
    asm("{ .reg .u64 t; cvta.to.shared.u64 t, %1; cvt.u32.u64 %0, t; }" : "=r"(a) : "l"(p));
    return a;
}
// pack two fp32 -> bf16x2 (RN); low half = lo
__device__ __forceinline__ uint32_t pack2(float lo, float hi) {
    uint32_t r;
    asm("cvt.rn.bf16x2.f32 %0, %1, %2;" : "=r"(r) : "f"(hi), "f"(lo));
    return r;
}
__device__ __forceinline__ uint4 lds128(uint32_t addr) {
    uint4 v;
    asm volatile("ld.shared.v4.b32 {%0,%1,%2,%3}, [%4];"
                 : "=r"(v.x), "=r"(v.y), "=r"(v.z), "=r"(v.w) : "r"(addr));
    return v;
}
__device__ __forceinline__ void cp16(uint32_t dst, const void* src) {
    asm volatile("cp.async.cg.shared.global [%0], [%1], 16;" :: "r"(dst), "l"(src));
}
#define CP_COMMIT() asm volatile("cp.async.commit_group;" ::: "memory")
#define CP_WAIT2()  asm volatile("cp.async.wait_group 2;" ::: "memory")

__device__ __forceinline__ void mma16(float* c,
    uint32_t a0, uint32_t a1, uint32_t a2, uint32_t a3, uint32_t b0, uint32_t b1)
{
    asm volatile(
        "mma.sync.aligned.m16n8k16.row.col.f32.bf16.bf16.f32 "
        "{%0,%1,%2,%3}, {%4,%5,%6,%7}, {%8,%9}, {%0,%1,%2,%3};"
        : "+f"(c[0]), "+f"(c[1]), "+f"(c[2]), "+f"(c[3])
        : "r"(a0), "r"(a1), "r"(a2), "r"(a3), "r"(b0), "r"(b1));
}

// ---------------- prepass: fp32 -> bf16 permuted rows ------------------------
// Permuted chunk row (64B = 16 bf16-pairs): 16B slot s holds pairs {s,s+4,s+8,s+12}
// (component q of slot s = pair q*4+s = bf16(k=2P), bf16(k=2P+1), P=q*4+s).
__global__ __launch_bounds__(256) void prepass(
    const float* __restrict__ x, const float* __restrict__ w1,
    const float* __restrict__ w2)
{
    int which = blockIdx.y;
    const float* src = which == 0 ? x : (which == 1 ? w1 : w2);
    uint4* dst = which == 0 ? g_xb : (which == 1 ? g_w1b : g_w2b);
    int idx = blockIdx.x * 256 + threadIdx.x;   // 8192 rows * 32 chunks
    int row = idx >> 5, c = idx & 31;

    const float4* s4 = (const float4*)(src + (size_t)row * HDIM + c * KC);
    float f[32];
#pragma unroll
    for (int i = 0; i < 8; i++) {
        float4 v = s4[i];
        f[4*i] = v.x; f[4*i+1] = v.y; f[4*i+2] = v.z; f[4*i+3] = v.w;
    }
    uint32_t p[16];
#pragma unroll
    for (int P = 0; P < 16; P++) p[P] = pack2(f[2*P], f[2*P+1]);
    uint4* drow = dst + ((size_t)row * 32 + c) * 4;
#pragma unroll
    for (int s = 0; s < 4; s++)
        drow[s] = make_uint4(p[s], p[s+4], p[s+8], p[s+12]);
}

// ---------------- router ------------------------------------------------------
__global__ __launch_bounds__(256) void router_kernel(
    const float* __restrict__ x, const float* __restrict__ rw,
    float* __restrict__ out, int write_probs)
{
    int t = blockIdx.x * 8 + (threadIdx.x >> 5);
    if (t >= T_TOK) return;
    int lane = threadIdx.x & 31;

    float acc[NEXP];
#pragma unroll
    for (int e = 0; e < NEXP; e++) acc[e] = 0.f;
    const float* xp = x + (size_t)t * HDIM;
    for (int i = lane; i < HDIM; i += 32) {
        float xv = xp[i];
#pragma unroll
        for (int e = 0; e < NEXP; e++)
            acc[e] = fmaf(xv, rw[e * HDIM + i], acc[e]);
    }
#pragma unroll
    for (int e = 0; e < NEXP; e++)
#pragma unroll
        for (int off = 16; off; off >>= 1)
            acc[e] += __shfl_xor_sync(0xffffffffu, acc[e], off);

    if (lane == 0) {
        float m = acc[0];
#pragma unroll
        for (int e = 1; e < NEXP; e++) m = fmaxf(m, acc[e]);
        float p[NEXP]; float s = 0.f;
#pragma unroll
        for (int e = 0; e < NEXP; e++) { p[e] = expf(acc[e] - m); s += p[e]; }
        float inv_s = 1.f / s;
#pragma unroll
        for (int e = 0; e < NEXP; e++) p[e] *= inv_s;

        if (write_probs) {
            float* pr = out + (size_t)T_TOK * HDIM + (size_t)t * NEXP;
#pragma unroll
            for (int e = 0; e < NEXP; e++) pr[e] = p[e];
        }
        int i0 = 0;
#pragma unroll
        for (int e = 1; e < NEXP; e++) if (p[e] > p[i0]) i0 = e;
        int i1 = (i0 == 0) ? 1 : 0;
#pragma unroll
        for (int e = 0; e < NEXP; e++) if (e != i0 && p[e] > p[i1]) i1 = e;

        float v0 = p[i0], v1 = p[i1];
        float invw = 1.f / (v0 + v1);
        int pos0 = atomicAdd(&g_cnt[i0], 1);
        if (pos0 < CAP) { g_tok[i0 * CAP + pos0] = t; g_wgt[i0 * CAP + pos0] = v0 * invw; }
        int pos1 = atomicAdd(&g_cnt[i1], 1);
        if (pos1 < CAP) { g_tok[i1 * CAP + pos1] = t; g_wgt[i1 * CAP + pos1] = v1 * invw; }
    }
}

// ---------------- per-chunk compute (bf16 HMMA) -------------------------------
__device__ __forceinline__ void compute_chunk(
    uint32_t sbase, float acc[2][8][4], int wm, int wn, int gid, int tig)
{
    uint32_t toff = (uint32_t)((tig ^ (gid & 3)) * 16);
    uint4 alo[2], ahi[2];
#pragma unroll
    for (int mi = 0; mi < 2; mi++) {
        uint32_t a0 = sbase + (wm * 32 + mi * 16 + gid) * 64 + toff;
        alo[mi] = lds128(a0);
        ahi[mi] = lds128(a0 + 8 * 64);
    }
#pragma unroll
    for (int nh = 0; nh < 2; nh++) {
        uint4 fb[4];
#pragma unroll
        for (int ni = 0; ni < 4; ni++) {
            int n = wn * 64 + (nh * 4 + ni) * 8 + gid;
            fb[ni] = lds128(sbase + 8192 + n * 64 + toff);
        }
#pragma unroll
        for (int mi = 0; mi < 2; mi++)
#pragma unroll
            for (int ni = 0; ni < 4; ni++) {
                float* c = acc[mi][nh * 4 + ni];
                mma16(c, alo[mi].x, ahi[mi].x, alo[mi].y, ahi[mi].y, fb[ni].x, fb[ni].y);
                mma16(c, alo[mi].z, ahi[mi].z, alo[mi].w, ahi[mi].w, fb[ni].z, fb[ni].w);
            }
    }
}

// stage chunk cc into buffer buf (thread covers 2 A slots + 2 B slots)
#define STAGE(cc, buf) do { \
    uint32_t _b = sb + (uint32_t)(buf) * STAGE_BYTES; \
    const char* _ar = asrc + (cc) * 64; \
    const char* _br = bsrc + (cc) * 64; \
    cp16(_b + aoff0, _ar + s0 * 16); \
    cp16(_b + aoff1, _ar + s1 * 16); \
    cp16(_b + 8192 + aoff0, _br + s0 * 16); \
    cp16(_b + 8192 + aoff1, _br + s1 * 16); \
} while (0)

// ---------------- GEMM1: h1b = relu(xb[gather] @ W1b^T + b1), bf16-permuted out
__global__ __launch_bounds__(256, 2) void gemm1_tc(const float* __restrict__ b1)
{
    extern __shared__ char smem[];
    int e = blockIdx.z;
    int count = min(g_cnt[e], CAP);
    int m0 = blockIdx.y * TM;
    if (m0 >= count) return;
    int n0 = blockIdx.x * TN;

    uint32_t sb = smem_u32(smem);
    int tid = threadIdx.x, wid = tid >> 5, lane = tid & 31;
    int wm = wid >> 1, wn = wid & 1, gid = lane >> 2, tig = lane & 3;

    int arow = tid & 127, sh = tid >> 7;
    int s0 = sh * 2, s1 = s0 + 1;
    uint32_t aoff0 = arow * 64 + ((s0 ^ (arow & 3)) * 16);
    uint32_t aoff1 = arow * 64 + ((s1 ^ (arow & 3)) * 16);

    int tok = g_tok[e * CAP + m0 + arow];          // stale slots = 0 (zero-init), safe
    const char* asrc = (const char*)g_xb + (size_t)tok * 2048;
    const char* bsrc = (const char*)g_w1b + (size_t)(e * HDIM + n0 + arow) * 2048;

    float acc[2][8][4];
#pragma unroll
    for (int mi = 0; mi < 2; mi++)
#pragma unroll
        for (int ni = 0; ni < 8; ni++)
#pragma unroll
            for (int q = 0; q < 4; q++) acc[mi][ni][q] = 0.f;

    STAGE(0, 0); CP_COMMIT();
    STAGE(1, 1); CP_COMMIT();
    STAGE(2, 2); CP_COMMIT();

    for (int c = 0; c < NCH; c++) {
        CP_WAIT2();
        __syncthreads();
        if (c + 3 < NCH) STAGE(c + 3, (c + 3) & 3);
        CP_COMMIT();
        compute_chunk(sb + (c & 3) * STAGE_BYTES, acc, wm, wn, gid, tig);
    }

    // epilogue: relu(acc + b1) -> g_h1b (bf16, permuted rows)
    const float* bb = b1 + e * HDIM + n0 + wn * 64 + tig * 2;
    float2 bias[8];
#pragma unroll
    for (int ni = 0; ni < 8; ni++) bias[ni] = *(const float2*)(bb + ni * 8);

#pragma unroll
    for (int mi = 0; mi < 2; mi++)
#pragma unroll
        for (int h = 0; h < 2; h++) {
            int r = m0 + wm * 32 + mi * 16 + h * 8 + gid;
            if (r < count) {
                char* rowp = (char*)g_h1b + (size_t)(e * CAP + r) * 2048 + tig * 16;
#pragma unroll
                for (int ch = 0; ch < 2; ch++) {
                    uint4 o;
                    uint32_t* oc = (uint32_t*)&o;
#pragma unroll
                    for (int q = 0; q < 4; q++) {
                        int ni = ch * 4 + q;
                        float v0 = fmaxf(acc[mi][ni][h * 2 + 0] + bias[ni].x, 0.f);
                        float v1 = fmaxf(acc[mi][ni][h * 2 + 1] + bias[ni].y, 0.f);
                        oc[q] = pack2(v0, v1);
                    }
                    *(uint4*)(rowp + (blockIdx.x * 4 + wn * 2 + ch) * 64) = o;
                }
            }
        }
}

// ---------------- GEMM2: out[tok] += w * (h1b @ W2b^T + b2) -------------------
__global__ __launch_bounds__(256, 2) void gemm2_tc(
    const float* __restrict__ b2, float* __restrict__ out)
{
    extern __shared__ char smem[];
    int e = blockIdx.z;
    int count = min(g_cnt[e], CAP);
    int m0 = blockIdx.y * TM;
    if (m0 >= count) return;
    int n0 = blockIdx.x * TN;

    uint32_t sb = smem_u32(smem);
    int tid = threadIdx.x, wid = tid >> 5, lane = tid & 31;
    int wm = wid >> 1, wn = wid & 1, gid = lane >> 2, tig = lane & 3;

    int arow = tid & 127, sh = tid >> 7;
    int s0 = sh * 2, s1 = s0 + 1;
    uint32_t aoff0 = arow * 64 + ((s0 ^ (arow & 3)) * 16);
    uint32_t aoff1 = arow * 64 + ((s1 ^ (arow & 3)) * 16);

    const char* asrc = (const char*)g_h1b + (size_t)(e * CAP + m0 + arow) * 2048;
    const char* bsrc = (const char*)g_w2b + (size_t)(e * HDIM + n0 + arow) * 2048;

    float acc[2][8][4];
#pragma unroll
    for (int mi = 0; mi < 2; mi++)
#pragma unroll
        for (int ni = 0; ni < 8; ni++)
#pragma unroll
            for (int q = 0; q < 4; q++) acc[mi][ni][q] = 0.f;

    STAGE(0, 0); CP_COMMIT();
    STAGE(1, 1); CP_COMMIT();
    STAGE(2, 2); CP_COMMIT();

    for (int c = 0; c < NCH; c++) {
        CP_WAIT2();
        __syncthreads();
        if (c + 3 < NCH) STAGE(c + 3, (c + 3) & 3);
        CP_COMMIT();
        compute_chunk(sb + (c & 3) * STAGE_BYTES, acc, wm, wn, gid, tig);
    }

    // epilogue: out[tok] += w * (acc + b2)
    const float* bb = b2 + e * HDIM + n0 + wn * 64 + tig * 2;
    float2 bias[8];
#pragma unroll
    for (int ni = 0; ni < 8; ni++) bias[ni] = *(const float2*)(bb + ni * 8);

#pragma unroll
    for (int mi = 0; mi < 2; mi++)
#pragma unroll
        for (int h = 0; h < 2; h++) {
            int r = m0 + wm * 32 + mi * 16 + h * 8 + gid;
            if (r < count) {
                int tok = g_tok[e * CAP + r];
                float wv = g_wgt[e * CAP + r];
                float* dp = out + (size_t)tok * HDIM + n0 + wn * 64 + tig * 2;
#pragma unroll
                for (int ni = 0; ni < 8; ni++) {
                    atomicAdd(dp + ni * 8 + 0, (acc[mi][ni][h * 2 + 0] + bias[ni].x) * wv);
                    atomicAdd(dp + ni * 8 + 1, (acc[mi][ni][h * 2 + 1] + bias[ni].y) * wv);
                }
            }
        }
}

// ---------------- launch ------------------------------------------------------
extern "C" void kernel_launch(void* const* d_in, const int* in_sizes, int n_in,
                              void* d_out, int out_size)
{
    const float* x  = (const float*)d_in[0];
    const float* rw = (const float*)d_in[1];
    const float* W1 = (const float*)d_in[2];
    const float* b1 = (const float*)d_in[3];
    const float* W2 = (const float*)d_in[4];
    const float* b2 = (const float*)d_in[5];
    float* out = (float*)d_out;

    void* cnt_addr = nullptr;
    cudaGetSymbolAddress(&cnt_addr, g_cnt);
    cudaMemsetAsync(cnt_addr, 0, NEXP * sizeof(int), 0);

    // residual: out starts as hidden_states; GEMM2 accumulates into it
    cudaMemcpyAsync(out, x, (size_t)T_TOK * HDIM * sizeof(float),
                    cudaMemcpyDeviceToDevice, 0);

    int write_probs = (out_size >= T_TOK * HDIM + T_TOK * NEXP) ? 1 : 0;
    router_kernel<<<T_TOK / 8, 256>>>(x, rw, out, write_probs);

    prepass<<<dim3(T_TOK * NCH / 256, 3), 256>>>(x, W1, W2);

    cudaFuncSetAttribute(gemm1_tc, cudaFuncAttributeMaxDynamicSharedMemorySize, SMEM_BYTES);
    cudaFuncSetAttribute(gemm2_tc, cudaFuncAttributeMaxDynamicSharedMemorySize, SMEM_BYTES);

    dim3 grid(HDIM / TN, CAP / TM, NEXP);
    gemm1_tc<<<grid, 256, SMEM_BYTES>>>(b1);
    gemm2_tc<<<grid, 256, SMEM_BYTES>>>(b2, out);
}

// round 5
// speedup vs baseline: 4.0499x; 1.1454x over previous
#include <cuda_runtime.h>
#include <cuda_bf16.h>
#include <cstdint>
#include <math.h>

// Problem constants
#define T_TOK 8192
#define HDIM  1024
#define NEXP  8
#define CAP   4096

// GEMM tiling: CTA 128x128, 4 warps of 64x64, K-chunk 32, 4-stage cp.async
#define TM 128
#define TN 128
#define KC 32
#define NCH 32
#define STAGE_BYTES 16384           // A 8KB + B 8KB (bf16, 64B per 32-k row)
#define SMEM_BYTES (4 * STAGE_BYTES)

// ---------------- scratch (device globals, zero-init at load) ---------------
__device__ int   g_cnt[NEXP];
__device__ int   g_tok[NEXP * CAP];
__device__ float g_wgt[NEXP * CAP];
__device__ uint4 g_xb [(size_t)T_TOK * 128];        // 16MB bf16 permuted x
__device__ uint4 g_w1b[(size_t)NEXP * HDIM * 128];  // 16MB
__device__ uint4 g_w2b[(size_t)NEXP * HDIM * 128];  // 16MB
__device__ uint4 g_h1b[(size_t)NEXP * CAP * 128];   // 64MB bf16 permuted h1

// ---------------- helpers ----------------------------------------------------
__device__ __forceinline__ uint32_t smem_u32(const void* p) {
    uint32_t a;
    asm("{ .reg .u64 t; cvta.to.shared.u64 t, %1; cvt.u32.u64 %0, t; }" : "=r"(a) : "l"(p));
    return a;
}
// pack two fp32 -> bf16x2 (RN); low half = lo
__device__ __forceinline__ uint32_t pack2(float lo, float hi) {
    uint32_t r;
    asm("cvt.rn.bf16x2.f32 %0, %1, %2;" : "=r"(r) : "f"(hi), "f"(lo));
    return r;
}
__device__ __forceinline__ uint4 lds128(uint32_t addr) {
    uint4 v;
    asm volatile("ld.shared.v4.b32 {%0,%1,%2,%3}, [%4];"
                 : "=r"(v.x), "=r"(v.y), "=r"(v.z), "=r"(v.w) : "r"(addr));
    return v;
}
__device__ __forceinline__ void cp16(uint32_t dst, const void* src) {
    asm volatile("cp.async.cg.shared.global [%0], [%1], 16;" :: "r"(dst), "l"(src));
}
#define CP_COMMIT() asm volatile("cp.async.commit_group;" ::: "memory")
#define CP_WAIT2()  asm volatile("cp.async.wait_group 2;" ::: "memory")

__device__ __forceinline__ void mma16(float* c,
    uint32_t a0, uint32_t a1, uint32_t a2, uint32_t a3, uint32_t b0, uint32_t b1)
{
    asm volatile(
        "mma.sync.aligned.m16n8k16.row.col.f32.bf16.bf16.f32 "
        "{%0,%1,%2,%3}, {%4,%5,%6,%7}, {%8,%9}, {%0,%1,%2,%3};"
        : "+f"(c[0]), "+f"(c[1]), "+f"(c[2]), "+f"(c[3])
        : "r"(a0), "r"(a1), "r"(a2), "r"(a3), "r"(b0), "r"(b1));
}

// ---------------- prepass: fp32 -> bf16 permuted rows ------------------------
// Permuted chunk row (64B = 16 bf16-pairs): 16B slot s holds pairs {s,s+4,s+8,s+12}
__global__ __launch_bounds__(256) void prepass(
    const float* __restrict__ x, const float* __restrict__ w1,
    const float* __restrict__ w2)
{
    int which = blockIdx.y;
    const float* src = which == 0 ? x : (which == 1 ? w1 : w2);
    uint4* dst = which == 0 ? g_xb : (which == 1 ? g_w1b : g_w2b);
    int idx = blockIdx.x * 256 + threadIdx.x;   // 8192 rows * 32 chunks
    int row = idx >> 5, c = idx & 31;

    const float4* s4 = (const float4*)(src + (size_t)row * HDIM + c * KC);
    float f[32];
#pragma unroll
    for (int i = 0; i < 8; i++) {
        float4 v = s4[i];
        f[4*i] = v.x; f[4*i+1] = v.y; f[4*i+2] = v.z; f[4*i+3] = v.w;
    }
    uint32_t p[16];
#pragma unroll
    for (int P = 0; P < 16; P++) p[P] = pack2(f[2*P], f[2*P+1]);
    uint4* drow = dst + ((size_t)row * 32 + c) * 4;
#pragma unroll
    for (int s = 0; s < 4; s++)
        drow[s] = make_uint4(p[s], p[s+4], p[s+8], p[s+12]);
}

// ---------------- router ------------------------------------------------------
__global__ __launch_bounds__(256) void router_kernel(
    const float* __restrict__ x, const float* __restrict__ rw,
    float* __restrict__ out, int write_probs)
{
    int t = blockIdx.x * 8 + (threadIdx.x >> 5);
    if (t >= T_TOK) return;
    int lane = threadIdx.x & 31;

    float acc[NEXP];
#pragma unroll
    for (int e = 0; e < NEXP; e++) acc[e] = 0.f;
    const float* xp = x + (size_t)t * HDIM;
    for (int i = lane; i < HDIM; i += 32) {
        float xv = xp[i];
#pragma unroll
        for (int e = 0; e < NEXP; e++)
            acc[e] = fmaf(xv, rw[e * HDIM + i], acc[e]);
    }
#pragma unroll
    for (int e = 0; e < NEXP; e++)
#pragma unroll
        for (int off = 16; off; off >>= 1)
            acc[e] += __shfl_xor_sync(0xffffffffu, acc[e], off);

    if (lane == 0) {
        float m = acc[0];
#pragma unroll
        for (int e = 1; e < NEXP; e++) m = fmaxf(m, acc[e]);
        float p[NEXP]; float s = 0.f;
#pragma unroll
        for (int e = 0; e < NEXP; e++) { p[e] = expf(acc[e] - m); s += p[e]; }
        float inv_s = 1.f / s;
#pragma unroll
        for (int e = 0; e < NEXP; e++) p[e] *= inv_s;

        if (write_probs) {
            float* pr = out + (size_t)T_TOK * HDIM + (size_t)t * NEXP;
#pragma unroll
            for (int e = 0; e < NEXP; e++) pr[e] = p[e];
        }
        int i0 = 0;
#pragma unroll
        for (int e = 1; e < NEXP; e++) if (p[e] > p[i0]) i0 = e;
        int i1 = (i0 == 0) ? 1 : 0;
#pragma unroll
        for (int e = 0; e < NEXP; e++) if (e != i0 && p[e] > p[i1]) i1 = e;

        float v0 = p[i0], v1 = p[i1];
        float invw = 1.f / (v0 + v1);
        int pos0 = atomicAdd(&g_cnt[i0], 1);
        if (pos0 < CAP) { g_tok[i0 * CAP + pos0] = t; g_wgt[i0 * CAP + pos0] = v0 * invw; }
        int pos1 = atomicAdd(&g_cnt[i1], 1);
        if (pos1 < CAP) { g_tok[i1 * CAP + pos1] = t; g_wgt[i1 * CAP + pos1] = v1 * invw; }
    }
}

// ---------------- per-chunk compute: 64x64 warp tile (bf16 HMMA) -------------
// Physical slot of logical slot s in row r is s ^ ((r>>1)&3)  (conflict-free
// for both warp STS phases and lds128 fragment phases).
__device__ __forceinline__ void compute_chunk(
    uint32_t sbase, float acc[4][8][4], int wm, int wn, int gid, int tig)
{
    uint32_t toff = (uint32_t)((tig ^ ((gid >> 1) & 3)) * 16);
    uint4 alo[4], ahi[4];
#pragma unroll
    for (int mi = 0; mi < 4; mi++) {
        uint32_t a0 = sbase + (wm * 64 + mi * 16 + gid) * 64 + toff;
        alo[mi] = lds128(a0);
        ahi[mi] = lds128(a0 + 8 * 64);
    }
#pragma unroll
    for (int ni = 0; ni < 8; ni++) {
        uint4 fb = lds128(sbase + 8192 + (wn * 64 + ni * 8 + gid) * 64 + toff);
#pragma unroll
        for (int mi = 0; mi < 4; mi++) {
            float* c = acc[mi][ni];
            mma16(c, alo[mi].x, ahi[mi].x, alo[mi].y, ahi[mi].y, fb.x, fb.y);
            mma16(c, alo[mi].z, ahi[mi].z, alo[mi].w, ahi[mi].w, fb.z, fb.w);
        }
    }
}

// stage chunk cc into buffer buf: thread covers rows {rh, rh+64} of A and B,
// logical slots {2h, 2h+1} (32B contiguous gmem per row per thread)
#define STAGE(cc, buf) do { \
    uint32_t _b = sb + (uint32_t)(buf) * STAGE_BYTES; \
    uint32_t _go = (uint32_t)(cc) * 64 + h * 32; \
    cp16(_b + oa0,          aL + _go); \
    cp16(_b + oa1,          aL + _go + 16); \
    cp16(_b + oa0 + 4096,   aH + _go); \
    cp16(_b + oa1 + 4096,   aH + _go + 16); \
    cp16(_b + 8192 + oa0,        bL + _go); \
    cp16(_b + 8192 + oa1,        bL + _go + 16); \
    cp16(_b + 8192 + oa0 + 4096, bH + _go); \
    cp16(_b + 8192 + oa1 + 4096, bH + _go + 16); \
} while (0)

// ---------------- GEMM1: h1b = relu(xb[gather] @ W1b^T + b1) -----------------
__global__ __launch_bounds__(128, 2) void gemm1_tc(const float* __restrict__ b1)
{
    extern __shared__ char smem[];
    int e = blockIdx.z;
    int count = min(g_cnt[e], CAP);
    int m0 = blockIdx.y * TM;
    if (m0 >= count) return;
    int n0 = blockIdx.x * TN;

    uint32_t sb = smem_u32(smem);
    int tid = threadIdx.x, wid = tid >> 5, lane = tid & 31;
    int wm = wid >> 1, wn = wid & 1, gid = lane >> 2, tig = lane & 3;

    // staging geometry
    int rh = tid >> 1, h = tid & 1;
    int sig = (rh >> 1) & 3;                 // same for rh and rh+64
    uint32_t oa0 = rh * 64 + (((2 * h)     ^ sig) * 16);
    uint32_t oa1 = rh * 64 + (((2 * h + 1) ^ sig) * 16);

    int tokL = g_tok[e * CAP + m0 + rh];
    int tokH = g_tok[e * CAP + m0 + rh + 64];     // stale slots = 0, masked later
    const char* aL = (const char*)g_xb + (size_t)tokL * 2048;
    const char* aH = (const char*)g_xb + (size_t)tokH * 2048;
    const char* bL = (const char*)g_w1b + (size_t)(e * HDIM + n0 + rh) * 2048;
    const char* bH = bL + (size_t)64 * 2048;

    float acc[4][8][4];
#pragma unroll
    for (int mi = 0; mi < 4; mi++)
#pragma unroll
        for (int ni = 0; ni < 8; ni++)
#pragma unroll
            for (int q = 0; q < 4; q++) acc[mi][ni][q] = 0.f;

    STAGE(0, 0); CP_COMMIT();
    STAGE(1, 1); CP_COMMIT();
    STAGE(2, 2); CP_COMMIT();

    for (int c = 0; c < NCH; c++) {
        CP_WAIT2();
        __syncthreads();
        if (c + 3 < NCH) STAGE(c + 3, (c + 3) & 3);
        CP_COMMIT();
        compute_chunk(sb + (c & 3) * STAGE_BYTES, acc, wm, wn, gid, tig);
    }

    // epilogue: relu(acc + b1) -> g_h1b (bf16, permuted logical rows)
    const float* bb = b1 + e * HDIM + n0 + wn * 64 + tig * 2;
    float2 bias[8];
#pragma unroll
    for (int ni = 0; ni < 8; ni++) bias[ni] = *(const float2*)(bb + ni * 8);

#pragma unroll
    for (int mi = 0; mi < 4; mi++)
#pragma unroll
        for (int ph = 0; ph < 2; ph++) {
            int r = m0 + wm * 64 + mi * 16 + ph * 8 + gid;
            if (r < count) {
                char* rowp = (char*)g_h1b + (size_t)(e * CAP + r) * 2048 + tig * 16;
#pragma unroll
                for (int ch = 0; ch < 2; ch++) {
                    uint4 o;
                    uint32_t* oc = (uint32_t*)&o;
#pragma unroll
                    for (int q = 0; q < 4; q++) {
                        int ni = ch * 4 + q;
                        float v0 = fmaxf(acc[mi][ni][ph * 2 + 0] + bias[ni].x, 0.f);
                        float v1 = fmaxf(acc[mi][ni][ph * 2 + 1] + bias[ni].y, 0.f);
                        oc[q] = pack2(v0, v1);
                    }
                    *(uint4*)(rowp + (blockIdx.x * 4 + wn * 2 + ch) * 64) = o;
                }
            }
        }
}

// ---------------- GEMM2: out[tok] += w * (h1b @ W2b^T + b2) -------------------
__global__ __launch_bounds__(128, 2) void gemm2_tc(
    const float* __restrict__ b2, float* __restrict__ out)
{
    extern __shared__ char smem[];
    int e = blockIdx.z;
    int count = min(g_cnt[e], CAP);
    int m0 = blockIdx.y * TM;
    if (m0 >= count) return;
    int n0 = blockIdx.x * TN;

    uint32_t sb = smem_u32(smem);
    int tid = threadIdx.x, wid = tid >> 5, lane = tid & 31;
    int wm = wid >> 1, wn = wid & 1, gid = lane >> 2, tig = lane & 3;

    int rh = tid >> 1, h = tid & 1;
    int sig = (rh >> 1) & 3;
    uint32_t oa0 = rh * 64 + (((2 * h)     ^ sig) * 16);
    uint32_t oa1 = rh * 64 + (((2 * h + 1) ^ sig) * 16);

    const char* aL = (const char*)g_h1b + (size_t)(e * CAP + m0 + rh) * 2048;
    const char* aH = aL + (size_t)64 * 2048;
    const char* bL = (const char*)g_w2b + (size_t)(e * HDIM + n0 + rh) * 2048;
    const char* bH = bL + (size_t)64 * 2048;

    float acc[4][8][4];
#pragma unroll
    for (int mi = 0; mi < 4; mi++)
#pragma unroll
        for (int ni = 0; ni < 8; ni++)
#pragma unroll
            for (int q = 0; q < 4; q++) acc[mi][ni][q] = 0.f;

    STAGE(0, 0); CP_COMMIT();
    STAGE(1, 1); CP_COMMIT();
    STAGE(2, 2); CP_COMMIT();

    for (int c = 0; c < NCH; c++) {
        CP_WAIT2();
        __syncthreads();
        if (c + 3 < NCH) STAGE(c + 3, (c + 3) & 3);
        CP_COMMIT();
        compute_chunk(sb + (c & 3) * STAGE_BYTES, acc, wm, wn, gid, tig);
    }

    // epilogue: out[tok] += w * (acc + b2)
    const float* bb = b2 + e * HDIM + n0 + wn * 64 + tig * 2;
    float2 bias[8];
#pragma unroll
    for (int ni = 0; ni < 8; ni++) bias[ni] = *(const float2*)(bb + ni * 8);

#pragma unroll
    for (int mi = 0; mi < 4; mi++)
#pragma unroll
        for (int ph = 0; ph < 2; ph++) {
            int r = m0 + wm * 64 + mi * 16 + ph * 8 + gid;
            if (r < count) {
                int tok = g_tok[e * CAP + r];
                float wv = g_wgt[e * CAP + r];
                float* dp = out + (size_t)tok * HDIM + n0 + wn * 64 + tig * 2;
#pragma unroll
                for (int ni = 0; ni < 8; ni++) {
                    atomicAdd(dp + ni * 8 + 0, (acc[mi][ni][ph * 2 + 0] + bias[ni].x) * wv);
                    atomicAdd(dp + ni * 8 + 1, (acc[mi][ni][ph * 2 + 1] + bias[ni].y) * wv);
                }
            }
        }
}

// ---------------- launch ------------------------------------------------------
extern "C" void kernel_launch(void* const* d_in, const int* in_sizes, int n_in,
                              void* d_out, int out_size)
{
    const float* x  = (const float*)d_in[0];
    const float* rw = (const float*)d_in[1];
    const float* W1 = (const float*)d_in[2];
    const float* b1 = (const float*)d_in[3];
    const float* W2 = (const float*)d_in[4];
    const float* b2 = (const float*)d_in[5];
    float* out = (float*)d_out;

    void* cnt_addr = nullptr;
    cudaGetSymbolAddress(&cnt_addr, g_cnt);
    cudaMemsetAsync(cnt_addr, 0, NEXP * sizeof(int), 0);

    // residual: out starts as hidden_states; GEMM2 accumulates into it
    cudaMemcpyAsync(out, x, (size_t)T_TOK * HDIM * sizeof(float),
                    cudaMemcpyDeviceToDevice, 0);

    int write_probs = (out_size >= T_TOK * HDIM + T_TOK * NEXP) ? 1 : 0;
    router_kernel<<<T_TOK / 8, 256>>>(x, rw, out, write_probs);

    prepass<<<dim3(T_TOK * NCH / 256, 3), 256>>>(x, W1, W2);

    cudaFuncSetAttribute(gemm1_tc, cudaFuncAttributeMaxDynamicSharedMemorySize, SMEM_BYTES);
    cudaFuncSetAttribute(gemm2_tc, cudaFuncAttributeMaxDynamicSharedMemorySize, SMEM_BYTES);

    dim3 grid(HDIM / TN, CAP / TM, NEXP);
    gemm1_tc<<<grid, 128, SMEM_BYTES>>>(b1);
    gemm2_tc<<<grid, 128, SMEM_BYTES>>>(b2, out);
}